// round 4
// baseline (speedup 1.0000x reference)
#include <cuda_runtime.h>
#include <math.h>

#define BATCH 16
#define CIN   512
#define NBOX  (64*64*9)      /* 36864 */
#define PRE   6000
#define POST  300
#define SORTN 8192
#define HBINS 16384
#define NEGV  (-1e30f)

// ---------------- device scratch (static; no runtime alloc) -----------------
__device__ float g_Wt[CIN*9*CIN];
__device__ float g_shared[(size_t)BATCH*CIN*64*64];
__device__ float g_boxes[(size_t)BATCH*NBOX*4];
__device__ float g_scores[(size_t)BATCH*NBOX];

// ---------------- K0: W[co][ci][k] -> Wt[ci][k][co] --------------------------
__global__ void k_transform(const float* __restrict__ Wsh) {
    int idx = blockIdx.x * blockDim.x + threadIdx.x;
    if (idx < CIN*CIN*9) {
        int k  = idx % 9;
        int ci = (idx / 9) % CIN;
        int co = idx / (9*CIN);
        g_Wt[(ci*9 + k)*CIN + co] = Wsh[idx];
    }
}

// ---------------- K1: 3x3 conv + bias + relu (fp32 FMA, fp64 master acc) ----
__global__ __launch_bounds__(256) void k_conv(const float* __restrict__ x,
                                              const float* __restrict__ bsh) {
    __shared__ __align__(16) float xs[8*10*12];
    __shared__ __align__(16) float ws[8*9*64];

    int t   = threadIdx.x;
    int x0  = blockIdx.x * 8;
    int y0  = blockIdx.y * 8;
    int b   = blockIdx.z >> 3;
    int co0 = (blockIdx.z & 7) * 64;
    int cg  = t & 15;
    int p   = t >> 4;
    int py  = p >> 1;
    int pxg = p & 1;

    double accd[16];
#pragma unroll
    for (int i = 0; i < 16; i++) accd[i] = 0.0;

    for (int cc = 0; cc < 64; cc++) {
        int ci0 = cc * 8;
        for (int idx = t; idx < 800; idx += 256) {
            int ci  = idx / 100;
            int rem = idx - ci*100;
            int yy  = rem / 10;
            int xx  = rem - yy*10;
            int gy  = y0 - 1 + yy;
            int gx  = x0 - 1 + xx;
            float v = 0.f;
            if (gy >= 0 && gy < 64 && gx >= 0 && gx < 64)
                v = x[(((size_t)b*CIN + ci0 + ci)*64 + gy)*64 + gx];
            xs[ci*120 + yy*12 + xx] = v;
        }
#pragma unroll
        for (int i = 0; i < 18; i++) {
            int lin = t + i*256;
            int co  = lin & 63;
            int r   = lin >> 6;
            int k   = r % 9;
            int ci  = r / 9;
            ws[(ci*9 + k)*64 + co] = g_Wt[((ci0 + ci)*9 + k)*CIN + co0 + co];
        }
        __syncthreads();

        float pacc[16];
#pragma unroll
        for (int i = 0; i < 16; i++) pacc[i] = 0.f;

#pragma unroll
        for (int ci = 0; ci < 8; ci++) {
#pragma unroll
            for (int ky = 0; ky < 3; ky++) {
                const float* xr = &xs[ci*120 + (py + ky)*12 + pxg*4];
                float xv[6];
#pragma unroll
                for (int m = 0; m < 6; m++) xv[m] = xr[m];
#pragma unroll
                for (int kx = 0; kx < 3; kx++) {
                    float4 w = *(const float4*)&ws[(ci*9 + ky*3 + kx)*64 + cg*4];
#pragma unroll
                    for (int j = 0; j < 4; j++) {
                        float xj = xv[kx + j];
                        pacc[j*4 + 0] += xj * w.x;
                        pacc[j*4 + 1] += xj * w.y;
                        pacc[j*4 + 2] += xj * w.z;
                        pacc[j*4 + 3] += xj * w.w;
                    }
                }
            }
        }
#pragma unroll
        for (int i = 0; i < 16; i++) accd[i] += (double)pacc[i];
        __syncthreads();
    }

#pragma unroll
    for (int c = 0; c < 4; c++) {
        int co = co0 + cg*4 + c;
        double bb = (double)bsh[co];
        float4 o;
        o.x = (float)fmax(accd[0  + c] + bb, 0.0);
        o.y = (float)fmax(accd[4  + c] + bb, 0.0);
        o.z = (float)fmax(accd[8  + c] + bb, 0.0);
        o.w = (float)fmax(accd[12 + c] + bb, 0.0);
        *(float4*)&g_shared[(((size_t)b*CIN + co)*64 + y0 + py)*64 + x0 + pxg*4] = o;
    }
}

// ---------------- K2: 1x1 heads; tail replicates reference fp32 per-op ------
__global__ __launch_bounds__(256) void k_heads(const float* __restrict__ Wc,
                                               const float* __restrict__ bc,
                                               const float* __restrict__ Wr,
                                               const float* __restrict__ br,
                                               float* __restrict__ out,
                                               size_t regbase, size_t clsbase,
                                               int write_regcls) {
    __shared__ __align__(16) float smem[4096 + 64*56];
    float* as_ = smem;
    float* wsm = smem + 4096;

    int y  = blockIdx.x;
    int b  = blockIdx.y;
    int t  = threadIdx.x;
    int px = t & 63;
    int cs = t >> 6;

    float acc[56];
#pragma unroll
    for (int i = 0; i < 56; i++) acc[i] = 0.f;

    for (int ch = 0; ch < 8; ch++) {
        int ci0 = ch * 64;
        for (int lin = t; lin < 4096; lin += 256) {
            int px2 = lin & 63;
            int ci  = lin >> 6;
            as_[ci*64 + px2] = g_shared[(((size_t)b*CIN + ci0 + ci)*64 + y)*64 + px2];
        }
        for (int lin = t; lin < 64*56; lin += 256) {
            int ci = lin & 63;
            int oc = lin >> 6;
            float v = 0.f;
            if (oc < 18)      v = Wc[oc*CIN + ci0 + ci];
            else if (oc < 54) v = Wr[(oc - 18)*CIN + ci0 + ci];
            wsm[ci*56 + oc] = v;
        }
        __syncthreads();

        int cbeg = cs * 16;
        for (int ci = cbeg; ci < cbeg + 16; ci++) {
            float a = as_[ci*64 + px];
            const float4* wp = (const float4*)&wsm[ci*56];
#pragma unroll
            for (int m = 0; m < 14; m++) {
                float4 w = wp[m];
                acc[4*m + 0] += a * w.x;
                acc[4*m + 1] += a * w.y;
                acc[4*m + 2] += a * w.z;
                acc[4*m + 3] += a * w.w;
            }
        }
        __syncthreads();
    }

    // cross-slice reduction in fp64, round once to fp32 (conv-output proxy)
    float* red = smem;
#pragma unroll
    for (int half = 0; half < 2; half++) {
#pragma unroll
        for (int o = 0; o < 28; o++)
            red[(cs*64 + px)*28 + o] = acc[half*28 + o];
        __syncthreads();
        if (cs == 0) {
#pragma unroll
            for (int o = 0; o < 28; o++)
                acc[half*28 + o] = (float)((double)red[(0*64 + px)*28 + o]
                                         + (double)red[(1*64 + px)*28 + o]
                                         + (double)red[(2*64 + px)*28 + o]
                                         + (double)red[(3*64 + px)*28 + o]);
        }
        __syncthreads();
    }

    if (cs == 0) {
        int xq = px;
        const double RL[3] = {0.5, 1.0, 2.0};
        const double SL[3] = {8.0, 16.0, 32.0};
        float sx = (float)xq * 16.f;
        float sy = (float)y  * 16.f;
#pragma unroll
        for (int a = 0; a < 9; a++) {
            int n = (y*64 + xq)*9 + a;
            // --- fp32 softmax exactly as jax.nn.softmax ---
            float l0 = __fadd_rn(acc[2*a],     bc[2*a]);
            float l1 = __fadd_rn(acc[2*a + 1], bc[2*a + 1]);
            float mm = fmaxf(l0, l1);
            float e0 = expf(__fsub_rn(l0, mm));
            float e1 = expf(__fsub_rn(l1, mm));
            float se = __fadd_rn(e0, e1);
            float p0 = __fdiv_rn(e0, se);
            float p1 = __fdiv_rn(e1, se);
            // --- fp32 deltas (conv + bias, per-op rounding) ---
            float d0 = __fadd_rn(acc[18 + 4*a + 0], br[4*a + 0]);
            float d1 = __fadd_rn(acc[18 + 4*a + 1], br[4*a + 1]);
            float d2 = __fadd_rn(acc[18 + 4*a + 2], br[4*a + 2]);
            float d3 = __fadd_rn(acc[18 + 4*a + 3], br[4*a + 3]);

            if (write_regcls) {
                size_t rb = regbase + ((size_t)b*NBOX + n)*4;
                out[rb + 0] = d0; out[rb + 1] = d1;
                out[rb + 2] = d2; out[rb + 3] = d3;
                size_t cb = clsbase + ((size_t)b*NBOX + n)*2;
                out[cb + 0] = p0; out[cb + 1] = p1;
            }

            // --- anchor base in fp64, rounded ONCE to fp32 (numpy semantics) ---
            double r = RL[a / 3], s = SL[a % 3];
            double hhd = 16.0 * s * sqrt(r);
            double wwd = 16.0 * s * sqrt(1.0 / r);
            float bx1 = (float)(8.0 - wwd*0.5);
            float by1 = (float)(8.0 - hhd*0.5);
            float bx2 = (float)(8.0 + wwd*0.5);
            float by2 = (float)(8.0 + hhd*0.5);
            // shift + base, fp32 add (jax semantics)
            float ax1 = __fadd_rn(sx, bx1);
            float ay1 = __fadd_rn(sy, by1);
            float ax2 = __fadd_rn(sx, bx2);
            float ay2 = __fadd_rn(sy, by2);
            // --- fp32 decode, per-op rounding, no FMA contraction ---
            float aw  = __fsub_rn(ax2, ax1);
            float ah  = __fsub_rn(ay2, ay1);
            float axc = __fadd_rn(ax1, 0.5f*aw);
            float ayc = __fadd_rn(ay1, 0.5f*ah);
            float cx  = __fadd_rn(__fmul_rn(d0, aw), axc);
            float cy  = __fadd_rn(__fmul_rn(d1, ah), ayc);
            float bw  = __fmul_rn(expf(d2), aw);
            float bh  = __fmul_rn(expf(d3), ah);
            float x1 = fminf(fmaxf(__fsub_rn(cx, 0.5f*bw), 0.f), 1024.f);
            float y1 = fminf(fmaxf(__fsub_rn(cy, 0.5f*bh), 0.f), 1024.f);
            float x2 = fminf(fmaxf(__fadd_rn(cx, 0.5f*bw), 0.f), 1024.f);
            float y2 = fminf(fmaxf(__fadd_rn(cy, 0.5f*bh), 0.f), 1024.f);
            float wd = __fsub_rn(x2, x1);
            float hd = __fsub_rn(y2, y1);
            float sc = (wd >= 16.f && hd >= 16.f) ? p1 : NEGV;

            size_t bo = (size_t)b*NBOX + n;
            g_scores[bo] = sc;
            float4 bv; bv.x = x1; bv.y = y1; bv.z = x2; bv.w = y2;
            *(float4*)&g_boxes[bo*4] = bv;
        }
    }
}

// ---------------- K3: exact top-6000 + bitonic sort + NMS (1 block/batch) ---
#define NMS_SMEM (65536 + 96000)

__global__ __launch_bounds__(1024) void k_nms(float* __restrict__ rois) {
    extern __shared__ __align__(16) unsigned char dsm[];
    unsigned long long* keys = (unsigned long long*)dsm;
    unsigned int*       hist = (unsigned int*)dsm;
    float4*             sb4  = (float4*)(dsm + 65536);
    __shared__ unsigned int csum[512];
    __shared__ unsigned int supp[188];
    __shared__ int ctrl[4];

    int b = blockIdx.x;
    int t = threadIdx.x;
    const float* scores = g_scores + (size_t)b * NBOX;

    for (int i = t; i < HBINS; i += 1024) hist[i] = 0u;
    if (t == 0) ctrl[0] = 0;
    __syncthreads();
    for (int i = t; i < NBOX; i += 1024) {
        float s = scores[i];
        if (s > -1e29f) {
            int bin = (int)(s * (float)HBINS);
            bin = bin < 0 ? 0 : (bin > HBINS-1 ? HBINS-1 : bin);
            atomicAdd(&hist[bin], 1u);
        }
    }
    __syncthreads();
    for (int c = t; c < 512; c += 1024) {
        unsigned int sv = 0;
        for (int j = 0; j < 32; j++) sv += hist[c*32 + j];
        csum[c] = sv;
    }
    __syncthreads();
    if (t == 0) {
        unsigned int acc = 0;
        int T = 0;
        int c = 511;
        for (; c >= 0; c--) {
            if (acc + csum[c] >= PRE) break;
            acc += csum[c];
        }
        if (c >= 0) {
            for (int bin = c*32 + 31; bin >= c*32; bin--) {
                acc += hist[bin];
                if (acc >= PRE) { T = bin; break; }
            }
        }
        ctrl[1] = T;
    }
    __syncthreads();
    int T = ctrl[1];

    for (int i = t; i < SORTN; i += 1024) keys[i] = 0ULL;
    __syncthreads();
    for (int i = t; i < NBOX; i += 1024) {
        float s = scores[i];
        if (s > -1e29f) {
            int bin = (int)(s * (float)HBINS);
            bin = bin < 0 ? 0 : (bin > HBINS-1 ? HBINS-1 : bin);
            if (bin >= T) {
                int pos = atomicAdd(&ctrl[0], 1);
                if (pos < SORTN)
                    keys[pos] = ((unsigned long long)__float_as_uint(s) << 32)
                              | (unsigned long long)(0xFFFFFFFFu - (unsigned)i);
            }
        }
    }
    __syncthreads();

    for (int k = 2; k <= SORTN; k <<= 1) {
        for (int j = k >> 1; j > 0; j >>= 1) {
            for (int i = t; i < SORTN; i += 1024) {
                int ixj = i ^ j;
                if (ixj > i) {
                    unsigned long long a = keys[i], c2 = keys[ixj];
                    bool desc = ((i & k) == 0);
                    if (desc ? (a < c2) : (a > c2)) { keys[i] = c2; keys[ixj] = a; }
                }
            }
            __syncthreads();
        }
    }

    int cnt = ctrl[0];
    if (cnt > SORTN) cnt = SORTN;
    int nsel = cnt < PRE ? cnt : PRE;

    for (int i = t; i < nsel; i += 1024) {
        unsigned idx = 0xFFFFFFFFu - (unsigned)(keys[i]);
        sb4[i] = *(const float4*)&g_boxes[((size_t)b*NBOX + idx)*4];
    }
    for (int i = t; i < 188; i += 1024) supp[i] = 0u;
    if (t == 0) ctrl[2] = 0;
    __syncthreads();

    for (int round = 0; round < POST; round++) {
        if (t == 0) {
            int cur = ctrl[2];
            while (cur < nsel && ((supp[cur >> 5] >> (cur & 31)) & 1u)) cur++;
            int sel = (cur < nsel) ? cur : -1;
            ctrl[3] = sel;
            size_t ro = ((size_t)b*POST + round)*5;
            if (sel >= 0) {
                float4 bv = sb4[sel];
                float sc = __uint_as_float((unsigned)(keys[sel] >> 32));
                rois[ro+0] = sc; rois[ro+1] = bv.x; rois[ro+2] = bv.y;
                rois[ro+3] = bv.z; rois[ro+4] = bv.w;
                ctrl[2] = cur + 1;
            } else {
                rois[ro+0] = 0.f; rois[ro+1] = 0.f; rois[ro+2] = 0.f;
                rois[ro+3] = 0.f; rois[ro+4] = 0.f;
            }
        }
        __syncthreads();
        int sel = ctrl[3];
        if (sel >= 0) {
            float4 bb = sb4[sel];
            // fp32 per-op rounding exactly as reference _iou_one
            float a1 = __fmul_rn(__fsub_rn(bb.z, bb.x), __fsub_rn(bb.w, bb.y));
            for (int j = sel + 1 + t; j < nsel; j += 1024) {
                if (((supp[j >> 5] >> (j & 31)) & 1u) == 0u) {
                    float4 c = sb4[j];
                    float iw = fmaxf(__fsub_rn(fminf(bb.z, c.z), fmaxf(bb.x, c.x)), 0.f);
                    float ih = fmaxf(__fsub_rn(fminf(bb.w, c.w), fmaxf(bb.y, c.y)), 0.f);
                    float inter = __fmul_rn(iw, ih);
                    float a2 = __fmul_rn(__fsub_rn(c.z, c.x), __fsub_rn(c.w, c.y));
                    float denom = __fadd_rn(__fsub_rn(__fadd_rn(a1, a2), inter), 1e-9f);
                    float iou = __fdiv_rn(inter, denom);
                    if (iou >= 0.7f) atomicOr(&supp[j >> 5], 1u << (j & 31));
                }
            }
        }
        __syncthreads();
    }
}

// ---------------- host launch ------------------------------------------------
extern "C" void kernel_launch(void* const* d_in, const int* in_sizes, int n_in,
                              void* d_out, int out_size) {
    const float* x   = (const float*)d_in[0];
    const float* Wsh = (const float*)d_in[1];
    const float* bsh = (const float*)d_in[2];
    const float* Wc  = (const float*)d_in[3];
    const float* bc  = (const float*)d_in[4];
    const float* Wr  = (const float*)d_in[5];
    const float* br  = (const float*)d_in[6];
    float* out = (float*)d_out;

    size_t regbase = 0, clsbase = 0, roibase = 0;
    int write_regcls = 1;
    if (out_size == (int)((size_t)BATCH*NBOX*4 + (size_t)BATCH*NBOX*2 + (size_t)BATCH*POST*5)) {
        regbase = 0;
        clsbase = (size_t)BATCH*NBOX*4;
        roibase = clsbase + (size_t)BATCH*NBOX*2;
    } else {
        write_regcls = 0;
        roibase = 0;
    }

    cudaFuncSetAttribute(k_nms, cudaFuncAttributeMaxDynamicSharedMemorySize, NMS_SMEM);

    k_transform<<<(CIN*CIN*9 + 255)/256, 256>>>(Wsh);
    k_conv<<<dim3(8, 8, BATCH*8), 256>>>(x, bsh);
    k_heads<<<dim3(64, BATCH), 256>>>(Wc, bc, Wr, br, out, regbase, clsbase, write_regcls);
    k_nms<<<BATCH, 1024, NMS_SMEM>>>(out + roibase);
}

// round 5
// speedup vs baseline: 1.1855x; 1.1855x over previous
#include <cuda_runtime.h>
#include <math.h>

#define BATCH 16
#define CIN   512
#define NBOX  (64*64*9)      /* 36864 */
#define PRE   6000
#define POST  300
#define SORTN 8192
#define HBINS 16384
#define NEGV  (-1e30f)

// ---------------- device scratch (static; no runtime alloc) -----------------
__device__ float g_Wt[CIN*9*CIN];
__device__ float g_shared[(size_t)BATCH*CIN*64*64];
__device__ float g_boxes[(size_t)BATCH*NBOX*4];
__device__ float g_scores[(size_t)BATCH*NBOX];

// ---------------- packed f32x2 helpers (sm_103a double-rate fp32) -----------
__device__ __forceinline__ void ffma2(unsigned long long& acc,
                                      unsigned long long a,
                                      unsigned long long b) {
    asm("fma.rn.f32x2 %0, %1, %2, %0;" : "+l"(acc) : "l"(a), "l"(b));
}
__device__ __forceinline__ unsigned long long pack2(float x, float y) {
    unsigned long long r;
    asm("mov.b64 %0, {%1, %2};" : "=l"(r) : "f"(x), "f"(y));
    return r;
}
__device__ __forceinline__ void unpack2(unsigned long long v, float& lo, float& hi) {
    asm("mov.b64 {%0, %1}, %2;" : "=f"(lo), "=f"(hi) : "l"(v));
}
__device__ __forceinline__ void lds_v2u64(unsigned long long& a,
                                          unsigned long long& b,
                                          unsigned addr) {
    asm volatile("ld.shared.v2.u64 {%0, %1}, [%2];" : "=l"(a), "=l"(b) : "r"(addr));
}

// ---------------- K0: W[co][ci][k] -> Wt[ci][k][co] --------------------------
__global__ void k_transform(const float* __restrict__ Wsh) {
    int idx = blockIdx.x * blockDim.x + threadIdx.x;
    if (idx < CIN*CIN*9) {
        int k  = idx % 9;
        int ci = (idx / 9) % CIN;
        int co = idx / (9*CIN);
        g_Wt[(ci*9 + k)*CIN + co] = Wsh[idx];
    }
}

// ---------------- K1: 3x3 conv + bias + relu (FFMA2 fp32, fp64 master acc) --
// block 256 thr; tile 64co x (8y x 8x); thread = 4co x 4px(x)
// Accumulators packed pairwise over co: lane order per accumulator identical
// to the scalar version => bit-identical numerics.
__global__ __launch_bounds__(256, 2) void k_conv(const float* __restrict__ x,
                                                 const float* __restrict__ bsh) {
    __shared__ __align__(16) float xs[8*10*12];
    __shared__ __align__(16) float ws[8*9*64];

    int t   = threadIdx.x;
    int x0  = blockIdx.x * 8;
    int y0  = blockIdx.y * 8;
    int b   = blockIdx.z >> 3;
    int co0 = (blockIdx.z & 7) * 64;
    int cg  = t & 15;
    int p   = t >> 4;
    int py  = p >> 1;
    int pxg = p & 1;

    unsigned ws_base = (unsigned)__cvta_generic_to_shared(ws) + (unsigned)(cg*4*4);

    double accd[16];
#pragma unroll
    for (int i = 0; i < 16; i++) accd[i] = 0.0;

    for (int cc = 0; cc < 64; cc++) {
        int ci0 = cc * 8;
        for (int idx = t; idx < 800; idx += 256) {
            int ci  = idx / 100;
            int rem = idx - ci*100;
            int yy  = rem / 10;
            int xx  = rem - yy*10;
            int gy  = y0 - 1 + yy;
            int gx  = x0 - 1 + xx;
            float v = 0.f;
            if (gy >= 0 && gy < 64 && gx >= 0 && gx < 64)
                v = x[(((size_t)b*CIN + ci0 + ci)*64 + gy)*64 + gx];
            xs[ci*120 + yy*12 + xx] = v;
        }
#pragma unroll
        for (int i = 0; i < 18; i++) {
            int lin = t + i*256;
            int co  = lin & 63;
            int r   = lin >> 6;
            int k   = r % 9;
            int ci  = r / 9;
            ws[(ci*9 + k)*64 + co] = g_Wt[((ci0 + ci)*9 + k)*CIN + co0 + co];
        }
        __syncthreads();

        // packed accumulators: accp[j*2+p] lanes = (co 2p, co 2p+1) for px j
        unsigned long long accp[8];
#pragma unroll
        for (int i = 0; i < 8; i++) accp[i] = 0ULL;

#pragma unroll
        for (int ci = 0; ci < 8; ci++) {
#pragma unroll
            for (int ky = 0; ky < 3; ky++) {
                const float* xr = &xs[ci*120 + (py + ky)*12 + pxg*4];
                float xv[6];
#pragma unroll
                for (int m = 0; m < 6; m++) xv[m] = xr[m];
                unsigned long long xp[6];
#pragma unroll
                for (int m = 0; m < 6; m++) xp[m] = pack2(xv[m], xv[m]);
                unsigned wrow = ws_base + (unsigned)((ci*9 + ky*3)*64*4);
#pragma unroll
                for (int kx = 0; kx < 3; kx++) {
                    unsigned long long w01, w23;
                    lds_v2u64(w01, w23, wrow + (unsigned)(kx*64*4));
#pragma unroll
                    for (int j = 0; j < 4; j++) {
                        ffma2(accp[j*2 + 0], xp[kx + j], w01);
                        ffma2(accp[j*2 + 1], xp[kx + j], w23);
                    }
                }
            }
        }
        // fold chunk partials into fp64 master accumulators (same as before)
#pragma unroll
        for (int j = 0; j < 4; j++) {
#pragma unroll
            for (int pp = 0; pp < 2; pp++) {
                float lo, hi;
                unpack2(accp[j*2 + pp], lo, hi);
                accd[j*4 + 2*pp + 0] += (double)lo;
                accd[j*4 + 2*pp + 1] += (double)hi;
            }
        }
        __syncthreads();
    }

#pragma unroll
    for (int c = 0; c < 4; c++) {
        int co = co0 + cg*4 + c;
        double bb = (double)bsh[co];
        float4 o;
        o.x = (float)fmax(accd[0  + c] + bb, 0.0);
        o.y = (float)fmax(accd[4  + c] + bb, 0.0);
        o.z = (float)fmax(accd[8  + c] + bb, 0.0);
        o.w = (float)fmax(accd[12 + c] + bb, 0.0);
        *(float4*)&g_shared[(((size_t)b*CIN + co)*64 + y0 + py)*64 + x0 + pxg*4] = o;
    }
}

// ---------------- K2: 1x1 heads; tail replicates reference fp32 per-op ------
__global__ __launch_bounds__(256) void k_heads(const float* __restrict__ Wc,
                                               const float* __restrict__ bc,
                                               const float* __restrict__ Wr,
                                               const float* __restrict__ br,
                                               float* __restrict__ out,
                                               size_t regbase, size_t clsbase,
                                               int write_regcls) {
    __shared__ __align__(16) float smem[4096 + 64*56];
    float* as_ = smem;
    float* wsm = smem + 4096;

    int y  = blockIdx.x;
    int b  = blockIdx.y;
    int t  = threadIdx.x;
    int px = t & 63;
    int cs = t >> 6;

    float acc[56];
#pragma unroll
    for (int i = 0; i < 56; i++) acc[i] = 0.f;

    for (int ch = 0; ch < 8; ch++) {
        int ci0 = ch * 64;
        for (int lin = t; lin < 4096; lin += 256) {
            int px2 = lin & 63;
            int ci  = lin >> 6;
            as_[ci*64 + px2] = g_shared[(((size_t)b*CIN + ci0 + ci)*64 + y)*64 + px2];
        }
        for (int lin = t; lin < 64*56; lin += 256) {
            int ci = lin & 63;
            int oc = lin >> 6;
            float v = 0.f;
            if (oc < 18)      v = Wc[oc*CIN + ci0 + ci];
            else if (oc < 54) v = Wr[(oc - 18)*CIN + ci0 + ci];
            wsm[ci*56 + oc] = v;
        }
        __syncthreads();

        int cbeg = cs * 16;
        for (int ci = cbeg; ci < cbeg + 16; ci++) {
            float a = as_[ci*64 + px];
            const float4* wp = (const float4*)&wsm[ci*56];
#pragma unroll
            for (int m = 0; m < 14; m++) {
                float4 w = wp[m];
                acc[4*m + 0] += a * w.x;
                acc[4*m + 1] += a * w.y;
                acc[4*m + 2] += a * w.z;
                acc[4*m + 3] += a * w.w;
            }
        }
        __syncthreads();
    }

    float* red = smem;
#pragma unroll
    for (int half = 0; half < 2; half++) {
#pragma unroll
        for (int o = 0; o < 28; o++)
            red[(cs*64 + px)*28 + o] = acc[half*28 + o];
        __syncthreads();
        if (cs == 0) {
#pragma unroll
            for (int o = 0; o < 28; o++)
                acc[half*28 + o] = (float)((double)red[(0*64 + px)*28 + o]
                                         + (double)red[(1*64 + px)*28 + o]
                                         + (double)red[(2*64 + px)*28 + o]
                                         + (double)red[(3*64 + px)*28 + o]);
        }
        __syncthreads();
    }

    if (cs == 0) {
        int xq = px;
        const double RL[3] = {0.5, 1.0, 2.0};
        const double SL[3] = {8.0, 16.0, 32.0};
        float sx = (float)xq * 16.f;
        float sy = (float)y  * 16.f;
#pragma unroll
        for (int a = 0; a < 9; a++) {
            int n = (y*64 + xq)*9 + a;
            float l0 = __fadd_rn(acc[2*a],     bc[2*a]);
            float l1 = __fadd_rn(acc[2*a + 1], bc[2*a + 1]);
            float mm = fmaxf(l0, l1);
            float e0 = expf(__fsub_rn(l0, mm));
            float e1 = expf(__fsub_rn(l1, mm));
            float se = __fadd_rn(e0, e1);
            float p0 = __fdiv_rn(e0, se);
            float p1 = __fdiv_rn(e1, se);
            float d0 = __fadd_rn(acc[18 + 4*a + 0], br[4*a + 0]);
            float d1 = __fadd_rn(acc[18 + 4*a + 1], br[4*a + 1]);
            float d2 = __fadd_rn(acc[18 + 4*a + 2], br[4*a + 2]);
            float d3 = __fadd_rn(acc[18 + 4*a + 3], br[4*a + 3]);

            if (write_regcls) {
                size_t rb = regbase + ((size_t)b*NBOX + n)*4;
                out[rb + 0] = d0; out[rb + 1] = d1;
                out[rb + 2] = d2; out[rb + 3] = d3;
                size_t cb = clsbase + ((size_t)b*NBOX + n)*2;
                out[cb + 0] = p0; out[cb + 1] = p1;
            }

            double r = RL[a / 3], s = SL[a % 3];
            double hhd = 16.0 * s * sqrt(r);
            double wwd = 16.0 * s * sqrt(1.0 / r);
            float bx1 = (float)(8.0 - wwd*0.5);
            float by1 = (float)(8.0 - hhd*0.5);
            float bx2 = (float)(8.0 + wwd*0.5);
            float by2 = (float)(8.0 + hhd*0.5);
            float ax1 = __fadd_rn(sx, bx1);
            float ay1 = __fadd_rn(sy, by1);
            float ax2 = __fadd_rn(sx, bx2);
            float ay2 = __fadd_rn(sy, by2);
            float aw  = __fsub_rn(ax2, ax1);
            float ah  = __fsub_rn(ay2, ay1);
            float axc = __fadd_rn(ax1, 0.5f*aw);
            float ayc = __fadd_rn(ay1, 0.5f*ah);
            float cx  = __fadd_rn(__fmul_rn(d0, aw), axc);
            float cy  = __fadd_rn(__fmul_rn(d1, ah), ayc);
            float bw  = __fmul_rn(expf(d2), aw);
            float bh  = __fmul_rn(expf(d3), ah);
            float x1 = fminf(fmaxf(__fsub_rn(cx, 0.5f*bw), 0.f), 1024.f);
            float y1 = fminf(fmaxf(__fsub_rn(cy, 0.5f*bh), 0.f), 1024.f);
            float x2 = fminf(fmaxf(__fadd_rn(cx, 0.5f*bw), 0.f), 1024.f);
            float y2 = fminf(fmaxf(__fadd_rn(cy, 0.5f*bh), 0.f), 1024.f);
            float wd = __fsub_rn(x2, x1);
            float hd = __fsub_rn(y2, y1);
            float sc = (wd >= 16.f && hd >= 16.f) ? p1 : NEGV;

            size_t bo = (size_t)b*NBOX + n;
            g_scores[bo] = sc;
            float4 bv; bv.x = x1; bv.y = y1; bv.z = x2; bv.w = y2;
            *(float4*)&g_boxes[bo*4] = bv;
        }
    }
}

// ---------------- K3: exact top-6000 + bitonic sort + NMS (1 block/batch) ---
#define NMS_SMEM (65536 + 96000)

__global__ __launch_bounds__(1024) void k_nms(float* __restrict__ rois) {
    extern __shared__ __align__(16) unsigned char dsm[];
    unsigned long long* keys = (unsigned long long*)dsm;
    unsigned int*       hist = (unsigned int*)dsm;
    float4*             sb4  = (float4*)(dsm + 65536);
    __shared__ unsigned int csum[512];
    __shared__ unsigned int supp[188];
    __shared__ int ctrl[4];

    int b = blockIdx.x;
    int t = threadIdx.x;
    const float* scores = g_scores + (size_t)b * NBOX;

    for (int i = t; i < HBINS; i += 1024) hist[i] = 0u;
    if (t == 0) ctrl[0] = 0;
    __syncthreads();
    for (int i = t; i < NBOX; i += 1024) {
        float s = scores[i];
        if (s > -1e29f) {
            int bin = (int)(s * (float)HBINS);
            bin = bin < 0 ? 0 : (bin > HBINS-1 ? HBINS-1 : bin);
            atomicAdd(&hist[bin], 1u);
        }
    }
    __syncthreads();
    for (int c = t; c < 512; c += 1024) {
        unsigned int sv = 0;
        for (int j = 0; j < 32; j++) sv += hist[c*32 + j];
        csum[c] = sv;
    }
    __syncthreads();
    if (t == 0) {
        unsigned int acc = 0;
        int T = 0;
        int c = 511;
        for (; c >= 0; c--) {
            if (acc + csum[c] >= PRE) break;
            acc += csum[c];
        }
        if (c >= 0) {
            for (int bin = c*32 + 31; bin >= c*32; bin--) {
                acc += hist[bin];
                if (acc >= PRE) { T = bin; break; }
            }
        }
        ctrl[1] = T;
    }
    __syncthreads();
    int T = ctrl[1];

    for (int i = t; i < SORTN; i += 1024) keys[i] = 0ULL;
    __syncthreads();
    for (int i = t; i < NBOX; i += 1024) {
        float s = scores[i];
        if (s > -1e29f) {
            int bin = (int)(s * (float)HBINS);
            bin = bin < 0 ? 0 : (bin > HBINS-1 ? HBINS-1 : bin);
            if (bin >= T) {
                int pos = atomicAdd(&ctrl[0], 1);
                if (pos < SORTN)
                    keys[pos] = ((unsigned long long)__float_as_uint(s) << 32)
                              | (unsigned long long)(0xFFFFFFFFu - (unsigned)i);
            }
        }
    }
    __syncthreads();

    for (int k = 2; k <= SORTN; k <<= 1) {
        for (int j = k >> 1; j > 0; j >>= 1) {
            for (int i = t; i < SORTN; i += 1024) {
                int ixj = i ^ j;
                if (ixj > i) {
                    unsigned long long a = keys[i], c2 = keys[ixj];
                    bool desc = ((i & k) == 0);
                    if (desc ? (a < c2) : (a > c2)) { keys[i] = c2; keys[ixj] = a; }
                }
            }
            __syncthreads();
        }
    }

    int cnt = ctrl[0];
    if (cnt > SORTN) cnt = SORTN;
    int nsel = cnt < PRE ? cnt : PRE;

    for (int i = t; i < nsel; i += 1024) {
        unsigned idx = 0xFFFFFFFFu - (unsigned)(keys[i]);
        sb4[i] = *(const float4*)&g_boxes[((size_t)b*NBOX + idx)*4];
    }
    for (int i = t; i < 188; i += 1024) supp[i] = 0u;
    if (t == 0) ctrl[2] = 0;
    __syncthreads();

    for (int round = 0; round < POST; round++) {
        if (t == 0) {
            int cur = ctrl[2];
            while (cur < nsel && ((supp[cur >> 5] >> (cur & 31)) & 1u)) cur++;
            int sel = (cur < nsel) ? cur : -1;
            ctrl[3] = sel;
            size_t ro = ((size_t)b*POST + round)*5;
            if (sel >= 0) {
                float4 bv = sb4[sel];
                float sc = __uint_as_float((unsigned)(keys[sel] >> 32));
                rois[ro+0] = sc; rois[ro+1] = bv.x; rois[ro+2] = bv.y;
                rois[ro+3] = bv.z; rois[ro+4] = bv.w;
                ctrl[2] = cur + 1;
            } else {
                rois[ro+0] = 0.f; rois[ro+1] = 0.f; rois[ro+2] = 0.f;
                rois[ro+3] = 0.f; rois[ro+4] = 0.f;
            }
        }
        __syncthreads();
        int sel = ctrl[3];
        if (sel >= 0) {
            float4 bb = sb4[sel];
            float a1 = __fmul_rn(__fsub_rn(bb.z, bb.x), __fsub_rn(bb.w, bb.y));
            for (int j = sel + 1 + t; j < nsel; j += 1024) {
                if (((supp[j >> 5] >> (j & 31)) & 1u) == 0u) {
                    float4 c = sb4[j];
                    float iw = fmaxf(__fsub_rn(fminf(bb.z, c.z), fmaxf(bb.x, c.x)), 0.f);
                    float ih = fmaxf(__fsub_rn(fminf(bb.w, c.w), fmaxf(bb.y, c.y)), 0.f);
                    float inter = __fmul_rn(iw, ih);
                    float a2 = __fmul_rn(__fsub_rn(c.z, c.x), __fsub_rn(c.w, c.y));
                    float denom = __fadd_rn(__fsub_rn(__fadd_rn(a1, a2), inter), 1e-9f);
                    float iou = __fdiv_rn(inter, denom);
                    if (iou >= 0.7f) atomicOr(&supp[j >> 5], 1u << (j & 31));
                }
            }
        }
        __syncthreads();
    }
}

// ---------------- host launch ------------------------------------------------
extern "C" void kernel_launch(void* const* d_in, const int* in_sizes, int n_in,
                              void* d_out, int out_size) {
    const float* x   = (const float*)d_in[0];
    const float* Wsh = (const float*)d_in[1];
    const float* bsh = (const float*)d_in[2];
    const float* Wc  = (const float*)d_in[3];
    const float* bc  = (const float*)d_in[4];
    const float* Wr  = (const float*)d_in[5];
    const float* br  = (const float*)d_in[6];
    float* out = (float*)d_out;

    size_t regbase = 0, clsbase = 0, roibase = 0;
    int write_regcls = 1;
    if (out_size == (int)((size_t)BATCH*NBOX*4 + (size_t)BATCH*NBOX*2 + (size_t)BATCH*POST*5)) {
        regbase = 0;
        clsbase = (size_t)BATCH*NBOX*4;
        roibase = clsbase + (size_t)BATCH*NBOX*2;
    } else {
        write_regcls = 0;
        roibase = 0;
    }

    cudaFuncSetAttribute(k_nms, cudaFuncAttributeMaxDynamicSharedMemorySize, NMS_SMEM);

    k_transform<<<(CIN*CIN*9 + 255)/256, 256>>>(Wsh);
    k_conv<<<dim3(8, 8, BATCH*8), 256>>>(x, bsh);
    k_heads<<<dim3(64, BATCH), 256>>>(Wc, bc, Wr, br, out, regbase, clsbase, write_regcls);
    k_nms<<<BATCH, 1024, NMS_SMEM>>>(out + roibase);
}